// round 15
// baseline (speedup 1.0000x reference)
#include <cuda_runtime.h>
#include <cuda_fp16.h>
#include <cstdint>

#define Bz 32
#define Lz 200
#define Dz 768
#define Sz 1556
#define ROWCAP (Bz*Lz)
#define FEATN (Bz*Lz*Dz)
#define WPER  (Dz*Dz)
#define WTOT (35*WPER)

// ---------------- device scratch (static, no allocs) ----------------
__device__ int  g_offsets[Bz*9];
__device__ int  g_rowbase[8*Bz];
__device__ int  g_Mk[8];
__device__ int2 g_rows[8*ROWCAP];
__device__ __half g_featF[FEATN];                 // 9.8MB
__device__ __half g_WtF[WTOT];                    // 41.3MB, K-major [z][o][kk]

struct Ptrs7 { const float* p[7]; };

// ---------------- helpers ----------------
__device__ __forceinline__ uint32_t s2u(const void* p) {
    uint32_t a;
    asm("{ .reg .u64 t; cvta.to.shared.u64 t, %1; cvt.u32.u64 %0, t; }" : "=r"(a) : "l"(p));
    return a;
}
__device__ __forceinline__ void cpasync16(uint32_t s, const void* g) {
    asm volatile("cp.async.cg.shared.global [%0], [%1], 16;" :: "r"(s), "l"(g));
}
__device__ __forceinline__ void ldsm4(uint32_t* r, uint32_t a) {
    asm volatile("ldmatrix.sync.aligned.m8n8.x4.shared.b16 {%0,%1,%2,%3}, [%4];"
        : "=r"(r[0]), "=r"(r[1]), "=r"(r[2]), "=r"(r[3]) : "r"(a));
}
__device__ __forceinline__ void mma16816(float* c, const uint32_t* a, const uint32_t* b) {
    asm volatile("mma.sync.aligned.m16n8k16.row.col.f32.f16.f16.f32 "
        "{%0,%1,%2,%3}, {%4,%5,%6,%7}, {%8,%9}, {%0,%1,%2,%3};"
        : "+f"(c[0]), "+f"(c[1]), "+f"(c[2]), "+f"(c[3])
        : "r"(a[0]), "r"(a[1]), "r"(a[2]), "r"(a[3]), "r"(b[0]), "r"(b[1]));
}

// ---------------- prep: weight transpose + feature fp16 + setup (fused) ----------------
#define WBLKS (7*Dz)            /* 5376 weight blocks: one per (z, o) */
#define FBLKS 1024
__global__ void prep(const float* __restrict__ feat, Ptrs7 w,
                     const int* __restrict__ mask) {
    __shared__ __half sw[Dz * 9];       // width (<=8) padded to odd stride (<=9)
    int bx = blockIdx.x;
    int tid = threadIdx.x;
    if (bx < WBLKS) {
        int z = bx / Dz, o = bx - z * Dz;
        int width = z + 2;
        int K = Dz * width;
        int W2 = width | 1;             // odd stride tames bank conflicts
        const float* src = w.p[z] + (long)o * K;
        for (int i = tid; i < K; i += 256) {
            int ii = i / width, j = i - ii * width;
            sw[ii * W2 + j] = __float2half_rn(src[i]);
        }
        __syncthreads();
        __half* dst = g_WtF + (long)(z * (z + 3) / 2) * WPER + (long)o * K;
        for (int i8 = tid; i8 < K / 8; i8 += 256) {
            int idx = i8 * 8;
            int j = idx / Dz, ii = idx - j * Dz;
            __half h[8];
            #pragma unroll
            for (int m = 0; m < 8; m++) h[m] = sw[(ii + m) * W2 + j];
            *(uint4*)(dst + idx) = *(uint4*)h;
        }
    } else if (bx < WBLKS + FBLKS) {
        // features: grid-stride over FEATN/8 uint4 groups
        int fb = bx - WBLKS;
        int stride = FBLKS * 256;
        for (int i = fb * 256 + tid; i < FEATN / 8; i += stride) {
            const float4* s = (const float4*)feat + (size_t)i * 2;
            float4 a = s[0], b = s[1];
            __half h[8];
            h[0] = __float2half_rn(a.x); h[1] = __float2half_rn(a.y);
            h[2] = __float2half_rn(a.z); h[3] = __float2half_rn(a.w);
            h[4] = __float2half_rn(b.x); h[5] = __float2half_rn(b.y);
            h[6] = __float2half_rn(b.z); h[7] = __float2half_rn(b.w);
            ((uint4*)g_featF)[i] = *(uint4*)h;
        }
    } else {
        // setup: lengths, offsets, per-k bases (one block)
        __shared__ int sh_n[Bz];
        if (tid < Bz) {
            int n = 0;
            #pragma unroll 8
            for (int i = 0; i < Lz; i++) n += mask[tid*Lz + i];
            sh_n[tid] = n;
            int off = 0;
            g_offsets[tid*9 + 0] = 0;
            #pragma unroll
            for (int k = 0; k < 8; k++) {
                int c = n - k - 2; if (c < 0) c = 0;
                off += c;
                g_offsets[tid*9 + k + 1] = off;
            }
        }
        __syncthreads();
        if (tid < 8) {
            int k = tid, run = 0;
            for (int b = 0; b < Bz; b++) {
                g_rowbase[k*Bz + b] = run;
                int c = sh_n[b] - k - 2; if (c < 0) c = 0;
                run += c;
            }
            g_Mk[k] = run;
        }
    }
}

// ---------------- finalize (fused build_rows): per-slot row-list entry,
//                   zero invalid rows, k0 copy, tail ----------------
__global__ void finalize(const float* __restrict__ feat, float* __restrict__ out,
                         int write_tail) {
    int idx = blockIdx.x;                 // 0 .. B*S-1
    int b = idx / Sz, s = idx % Sz;
    const int* off = &g_offsets[b*9];
    int k = 0;
    #pragma unroll
    for (int m = 1; m < 8; m++) k += (off[m] <= s);
    int valid = (s < off[8]);
    if (threadIdx.x == 0 && valid && k >= 1) {
        int rel = s - off[k];
        int r = g_rowbase[k*Bz + b] + rel;
        g_rows[k*ROWCAP + r] = make_int2(b*Lz + rel + 1, idx);
    }
    if (!valid) {
        float4* d = (float4*)(out + (size_t)idx * Dz);
        d[threadIdx.x] = make_float4(0.f, 0.f, 0.f, 0.f);
    } else if (k == 0) {
        // bucket 0: exact fp32 copy of feat row b*Lz + s + 1
        const float4* srow = (const float4*)(feat + ((size_t)b * Lz + s + 1) * Dz);
        float4* d = (float4*)(out + (size_t)idx * Dz);
        d[threadIdx.x] = srow[threadIdx.x];
    }
    if (write_tail && threadIdx.x == 0)
        out[(size_t)Bz*Sz*Dz + idx] = valid ? 1.0f : 0.0f;
}

// ---------------- fp16 single-pass mma.sync gathered GEMM, buckets k=1..7 ----------------
// CTA tile 256x128, 512 thr (4x4 warps, warp tile 64x32). K-chunk 32 fp16,
// 64B packed rows + XOR swizzle. 6 stages x 24KB; ONE barrier per 2-chunk iter,
// prefetch issued immediately after the barrier (before compute).
#define TILE_A  16384           /* A: 256 rows x 64B */
#define STAGE_B 24576           /* A @0, B @16K (128 rows x 64B) */
#define NSTG 6
#define SMEMREQ (NSTG*STAGE_B)
__device__ __forceinline__ int wrap6(int x) { return x >= NSTG ? x - NSTG : x; }
__global__ void __launch_bounds__(512, 1) mma_gemm(Ptrs7 bias, float* __restrict__ out) {
    int z = 6 - blockIdx.z;             // heavy buckets first
    int Mk = g_Mk[z + 1];
    int m0 = blockIdx.y * 256;
    if (m0 >= Mk) return;
    int Ktot = Dz * (z + 2);
    int n0 = blockIdx.x * 128;
    int t = threadIdx.x;
    int w = t >> 5, lane = t & 31;
    int wm = w >> 2, wn = w & 3;        // 4 x 4 warp grid

    __shared__ int s_src[256], s_dst[256];
    extern __shared__ __align__(16) char smem[];
    uint32_t smem_u = s2u(smem);

    if (t < 256) {
        int gr = m0 + t;
        if (gr < Mk) {
            int2 rc = g_rows[(z+1)*ROWCAP + gr];
            s_src[t] = rc.x * Dz;
            s_dst[t] = rc.y;
        } else { s_src[t] = 0; s_dst[t] = -1; }
    }
    __syncthreads();

    // A loader: thread t -> row t>>1 (0..255), 16B units cq, cq+1 (cq=(t&1)*2)
    int rA = t >> 1, cq = (t & 1) << 1;
    int swA = (rA >> 1) & 3;
    uint32_t offA0 = (uint32_t)rA * 64 + (uint32_t)((cq       ^ swA) << 4);
    uint32_t offA1 = (uint32_t)rA * 64 + (uint32_t)(((cq + 1) ^ swA) << 4);
    const __half* gA = g_featF + s_src[rA] + cq*8;
    // B loader: thread t -> row t>>2 (0..127), unit t&3
    int rB = t >> 2, cB = t & 3;
    int swB = (rB >> 1) & 3;
    uint32_t offB = 16384 + (uint32_t)rB * 64 + (uint32_t)((cB ^ swB) << 4);
    const __half* gB = g_WtF + (long)(z*(z+3)/2) * WPER + (long)(n0 + rB) * Ktot + cB*8;

    // ldmatrix per-lane bases
    int l8 = lane & 7;
    int rowA = wm*64 + l8 + ((lane >> 3) & 1) * 8;
    uint32_t swzA = (uint32_t)((rowA >> 1) & 3);
    uint32_t cA0 = (lane >> 4) & 1;
    uint32_t aRow[4];
    #pragma unroll
    for (int mf = 0; mf < 4; mf++) aRow[mf] = (uint32_t)(rowA + mf*16) * 64;
    // B as x4 pair frags: pairSel=(lane>>4)&1 rows +8, colSel=(lane>>3)&1 k-half
    int rowB4 = wn*32 + l8 + ((lane >> 4) & 1) * 8;
    uint32_t swzB = (uint32_t)((rowB4 >> 1) & 3);
    uint32_t cB0 = (lane >> 3) & 1;
    uint32_t bRow[2];
    #pragma unroll
    for (int pb = 0; pb < 2; pb++) bRow[pb] = (uint32_t)(rowB4 + pb*16) * 64;

    float acc[4][4][4];
    #pragma unroll
    for (int i = 0; i < 4; i++)
        #pragma unroll
        for (int j = 0; j < 4; j++)
            #pragma unroll
            for (int r = 0; r < 4; r++) acc[i][j][r] = 0.f;

    int nch = Ktot / 32;                // 24*(z+2): even, >= 48

    // prologue: chunks 0..3 -> stages 0..3
    #pragma unroll
    for (int p = 0; p < 4; p++) {
        uint32_t sb = smem_u + (uint32_t)p * STAGE_B;
        int ko = p * 32;
        cpasync16(sb + offA0, gA + ko); cpasync16(sb + offA1, gA + ko + 8);
        cpasync16(sb + offB,  gB + ko);
        asm volatile("cp.async.commit_group;" ::: "memory");
    }

    int s0 = 0;                         // stage of chunk c (mod 6)
    #pragma unroll 1
    for (int c = 0; c < nch; c += 2) {
        asm volatile("cp.async.wait_group 2;" ::: "memory");   // chunks c, c+1 landed
        __syncthreads();                                       // single barrier per iter

        // issue prefetch of chunks c+4, c+5 into stages (s0+4)%6, (s0+5)%6
        int pst = wrap6(s0 + 4);
        #pragma unroll
        for (int h = 0; h < 2; h++) {
            int cc = c + 4 + h;
            if (cc < nch) {
                uint32_t nb = smem_u + (uint32_t)wrap6(pst + h) * STAGE_B;
                int ko = cc * 32;
                cpasync16(nb + offA0, gA + ko); cpasync16(nb + offA1, gA + ko + 8);
                cpasync16(nb + offB,  gB + ko);
            }
            asm volatile("cp.async.commit_group;" ::: "memory");
        }

        // compute chunks c, c+1
        #pragma unroll
        for (int h = 0; h < 2; h++) {
            uint32_t sb = smem_u + (uint32_t)wrap6(s0 + h) * STAGE_B;
            #pragma unroll
            for (int ks = 0; ks < 2; ks++) {
                uint32_t colA = ((cA0 + 2*ks) ^ swzA) << 4;
                uint32_t colB = ((cB0 + 2*ks) ^ swzB) << 4;
                uint32_t af[4][4], bf[2][4];
                #pragma unroll
                for (int mf = 0; mf < 4; mf++) ldsm4(af[mf], sb + aRow[mf] + colA);
                #pragma unroll
                for (int pb = 0; pb < 2; pb++) ldsm4(bf[pb], sb + 16384 + bRow[pb] + colB);
                #pragma unroll
                for (int mf = 0; mf < 4; mf++) {
                    mma16816(acc[mf][0], af[mf], &bf[0][0]);
                    mma16816(acc[mf][1], af[mf], &bf[0][2]);
                    mma16816(acc[mf][2], af[mf], &bf[1][0]);
                    mma16816(acc[mf][3], af[mf], &bf[1][2]);
                }
            }
        }
        s0 = wrap6(s0 + 2);
    }
    asm volatile("cp.async.wait_group 0;" ::: "memory");

    // epilogue: bias + scatter to gathered dst rows
    int r0 = wm*64 + (lane >> 2);
    int cb = n0 + wn*32 + ((lane & 3) << 1);
    const float* bpz = bias.p[z];
    #pragma unroll
    for (int mf = 0; mf < 4; mf++) {
        int row = r0 + mf*16;
        int d0 = s_dst[row], d1 = s_dst[row + 8];
        #pragma unroll
        for (int nf = 0; nf < 4; nf++) {
            float2 bv = *(const float2*)(bpz + cb + nf*8);
            if (d0 >= 0) {
                float2 v; v.x = acc[mf][nf][0] + bv.x; v.y = acc[mf][nf][1] + bv.y;
                *(float2*)(out + (long)d0*Dz + cb + nf*8) = v;
            }
            if (d1 >= 0) {
                float2 v; v.x = acc[mf][nf][2] + bv.x; v.y = acc[mf][nf][3] + bv.y;
                *(float2*)(out + (long)d1*Dz + cb + nf*8) = v;
            }
        }
    }
}

// ---------------- launch ----------------
extern "C" void kernel_launch(void* const* d_in, const int* in_sizes, int n_in,
                              void* d_out, int out_size) {
    const float* feat = (const float*)d_in[0];
    const int*   mask = (const int*)d_in[1];
    // d_in[2] = span_mask (unused; shape only)

    Ptrs7 wp, bp;
    int wi = 0, bi = 0;
    for (int i = 3; i < n_in && i < 17; i++) {
        if (in_sizes[i] == Dz) { if (bi < 7) bp.p[bi++] = (const float*)d_in[i]; }
        else                   { if (wi < 7) wp.p[wi++] = (const float*)d_in[i]; }
    }
    float* out = (float*)d_out;

    prep<<<WBLKS + FBLKS + 1, 256>>>(feat, wp, mask);                  // launch 1 (incl setup)

    int tail = (out_size >= Bz*Sz*Dz + Bz*Sz) ? 1 : 0;
    finalize<<<Bz*Sz, 192>>>(feat, out, tail);                         // launch 2 (incl build_rows)

    cudaFuncSetAttribute(mma_gemm, cudaFuncAttributeMaxDynamicSharedMemorySize, SMEMREQ);
    mma_gemm<<<dim3(6, 25, 7), 512, SMEMREQ>>>(bp, out);               // launch 3
}

// round 16
// speedup vs baseline: 1.0413x; 1.0413x over previous
#include <cuda_runtime.h>
#include <cuda_fp16.h>
#include <cstdint>

#define Bz 32
#define Lz 200
#define Dz 768
#define Sz 1556
#define FEATN (Bz*Lz*Dz)
#define WPER  (Dz*Dz)
#define WTOT (35*WPER)

// ---------------- device scratch (static, no allocs) ----------------
__device__ int  g_offsets[Bz*9];
__device__ int  g_rowbase[8*Bz];
__device__ int  g_Mk[8];
__device__ __half g_featF[FEATN];                 // 9.8MB
__device__ __half g_WtF[WTOT];                    // 41.3MB, K-major [z][o][kk]

struct Ptrs7 { const float* p[7]; };

// ---------------- helpers ----------------
__device__ __forceinline__ uint32_t s2u(const void* p) {
    uint32_t a;
    asm("{ .reg .u64 t; cvta.to.shared.u64 t, %1; cvt.u32.u64 %0, t; }" : "=r"(a) : "l"(p));
    return a;
}
__device__ __forceinline__ void cpasync16(uint32_t s, const void* g) {
    asm volatile("cp.async.cg.shared.global [%0], [%1], 16;" :: "r"(s), "l"(g));
}
__device__ __forceinline__ void ldsm4(uint32_t* r, uint32_t a) {
    asm volatile("ldmatrix.sync.aligned.m8n8.x4.shared.b16 {%0,%1,%2,%3}, [%4];"
        : "=r"(r[0]), "=r"(r[1]), "=r"(r[2]), "=r"(r[3]) : "r"(a));
}
__device__ __forceinline__ void mma16816(float* c, const uint32_t* a, const uint32_t* b) {
    asm volatile("mma.sync.aligned.m16n8k16.row.col.f32.f16.f16.f32 "
        "{%0,%1,%2,%3}, {%4,%5,%6,%7}, {%8,%9}, {%0,%1,%2,%3};"
        : "+f"(c[0]), "+f"(c[1]), "+f"(c[2]), "+f"(c[3])
        : "r"(a[0]), "r"(a[1]), "r"(a[2]), "r"(a[3]), "r"(b[0]), "r"(b[1]));
}

// ---------------- prep: weight transpose (j-major smem, vector out)
//                   + feature fp16 + setup (fused) ----------------
#define WBLKS (7*Dz)            /* 5376 weight blocks: one per (z, o) */
#define FBLKS 1024
#define JSTRIDE 776             /* 768 + 8 pad; 1552B row, 16B-aligned */
__global__ void prep(const float* __restrict__ feat, Ptrs7 w,
                     const int* __restrict__ mask) {
    __shared__ __align__(16) __half sw[8 * JSTRIDE];
    int bx = blockIdx.x;
    int tid = threadIdx.x;
    if (bx < WBLKS) {
        int z = bx / Dz, o = bx - z * Dz;
        int width = z + 2;
        int K = Dz * width;
        const float* src = w.p[z] + (long)o * K;
        // coalesced load + convert, scatter to j-major smem
        for (int i = tid; i < K; i += 256) {
            int ii = i / width, j = i - ii * width;
            sw[j * JSTRIDE + ii] = __float2half_rn(src[i]);
        }
        __syncthreads();
        // vectorized out: dst[j*768 + ii..ii+7] = sw[j*776 + ii..ii+7]
        __half* dst = g_WtF + (long)(z * (z + 3) / 2) * WPER + (long)o * K;
        for (int i8 = tid; i8 < K / 8; i8 += 256) {
            int idx = i8 * 8;
            int j = idx / Dz, ii = idx - j * Dz;
            *(uint4*)(dst + idx) = *(const uint4*)(sw + j * JSTRIDE + ii);
        }
    } else if (bx < WBLKS + FBLKS) {
        // features: grid-stride over FEATN/8 uint4 groups
        int fb = bx - WBLKS;
        int stride = FBLKS * 256;
        for (int i = fb * 256 + tid; i < FEATN / 8; i += stride) {
            const float4* s = (const float4*)feat + (size_t)i * 2;
            float4 a = s[0], b = s[1];
            __half h[8];
            h[0] = __float2half_rn(a.x); h[1] = __float2half_rn(a.y);
            h[2] = __float2half_rn(a.z); h[3] = __float2half_rn(a.w);
            h[4] = __float2half_rn(b.x); h[5] = __float2half_rn(b.y);
            h[6] = __float2half_rn(b.z); h[7] = __float2half_rn(b.w);
            ((uint4*)g_featF)[i] = *(uint4*)h;
        }
    } else {
        // setup: lengths, offsets, per-k bases (one block)
        __shared__ int sh_n[Bz];
        if (tid < Bz) {
            int n = 0;
            #pragma unroll 8
            for (int i = 0; i < Lz; i++) n += mask[tid*Lz + i];
            sh_n[tid] = n;
            int off = 0;
            g_offsets[tid*9 + 0] = 0;
            #pragma unroll
            for (int k = 0; k < 8; k++) {
                int c = n - k - 2; if (c < 0) c = 0;
                off += c;
                g_offsets[tid*9 + k + 1] = off;
            }
        }
        __syncthreads();
        if (tid < 8) {
            int k = tid, run = 0;
            for (int b = 0; b < Bz; b++) {
                g_rowbase[k*Bz + b] = run;
                int c = sh_n[b] - k - 2; if (c < 0) c = 0;
                run += c;
            }
            g_Mk[k] = run;
        }
    }
}

// ---------------- fused GEMM + scattered finalize, buckets k=1..7 ----------------
// Prologue: each CTA fires ~48 slots of finalize stores (zero invalid rows, k0 copy,
// tail) -- fire-and-forget, drains under the mainloop (DRAM is ~2% busy).
// GEMM: CTA tile 256x128, 512 thr (4x4 warps, 64x32 warp tiles), K-chunk 32,
// 64B rows + XOR swizzle, 4 stages x 24KB, wait+barrier per 2 chunks.
// Row->(src,dst) derived by scanning g_rowbase (no g_rows array).
#define TILE_A  16384           /* A: 256 rows x 64B */
#define STAGE_B 24576           /* A @0, B @16K (128 rows x 64B) */
#define SMEMREQ (4*STAGE_B)
__global__ void __launch_bounds__(512, 1) mma_gemm(Ptrs7 bias, const float* __restrict__ feat,
                                                   float* __restrict__ out, int wtail) {
    int z = 6 - blockIdx.z;             // heavy buckets first
    int t = threadIdx.x;

    // ---- scattered finalize prologue (independent of GEMM work) ----
    {
        int cid = blockIdx.z * 150 + blockIdx.y * 6 + blockIdx.x;   // 0..1049
        int sub = t >> 8, st = t & 255;
        for (int q = cid * 2 + sub; q < Bz*Sz; q += 2100) {
            int b = q / Sz, s = q - b * Sz;
            const int* off = &g_offsets[b*9];
            int valid = (s < off[8]);
            if (st < 192) {
                if (!valid) {
                    float4* d = (float4*)(out + (size_t)q * Dz);
                    d[st] = make_float4(0.f, 0.f, 0.f, 0.f);
                } else if (s < off[1]) {    // bucket 0: exact fp32 copy
                    const float4* sr = (const float4*)(feat + ((size_t)b * Lz + s + 1) * Dz);
                    ((float4*)(out + (size_t)q * Dz))[st] = sr[st];
                }
            } else if (st == 192 && wtail) {
                out[(size_t)Bz*Sz*Dz + q] = valid ? 1.0f : 0.0f;
            }
        }
    }

    int Mk = g_Mk[z + 1];
    int m0 = blockIdx.y * 256;
    if (m0 >= Mk) return;
    int Ktot = Dz * (z + 2);
    int n0 = blockIdx.x * 128;
    int w = t >> 5, lane = t & 31;
    int wm = w >> 2, wn = w & 3;        // 4 x 4 warp grid

    __shared__ int s_src[256], s_dst[256];
    extern __shared__ __align__(16) char smem[];
    uint32_t smem_u = s2u(smem);

    if (t < 256) {
        int gr = m0 + t;
        if (gr < Mk) {
            const int* rb = &g_rowbase[(z + 1) * Bz];
            int b = 0;
            #pragma unroll
            for (int m = 1; m < Bz; m++) b += (rb[m] <= gr);
            int rel = gr - rb[b];
            s_src[t] = (b * Lz + rel + 1) * Dz;
            s_dst[t] = b * Sz + g_offsets[b * 9 + z + 1] + rel;
        } else { s_src[t] = 0; s_dst[t] = -1; }
    }
    __syncthreads();

    // A loader: thread t -> row t>>1 (0..255), 16B units cq, cq+1 (cq=(t&1)*2)
    int rA = t >> 1, cq = (t & 1) << 1;
    int swA = (rA >> 1) & 3;
    uint32_t offA0 = (uint32_t)rA * 64 + (uint32_t)((cq       ^ swA) << 4);
    uint32_t offA1 = (uint32_t)rA * 64 + (uint32_t)(((cq + 1) ^ swA) << 4);
    const __half* gA = g_featF + s_src[rA] + cq*8;
    // B loader: thread t -> row t>>2 (0..127), unit t&3
    int rB = t >> 2, cB = t & 3;
    int swB = (rB >> 1) & 3;
    uint32_t offB = 16384 + (uint32_t)rB * 64 + (uint32_t)((cB ^ swB) << 4);
    const __half* gB = g_WtF + (long)(z*(z+3)/2) * WPER + (long)(n0 + rB) * Ktot + cB*8;

    // ldmatrix per-lane bases
    int l8 = lane & 7;
    int rowA = wm*64 + l8 + ((lane >> 3) & 1) * 8;
    uint32_t swzA = (uint32_t)((rowA >> 1) & 3);
    uint32_t cA0 = (lane >> 4) & 1;
    uint32_t aRow[4];
    #pragma unroll
    for (int mf = 0; mf < 4; mf++) aRow[mf] = (uint32_t)(rowA + mf*16) * 64;
    // B as x4 pair frags: pairSel=(lane>>4)&1 rows +8, colSel=(lane>>3)&1 k-half
    int rowB4 = wn*32 + l8 + ((lane >> 4) & 1) * 8;
    uint32_t swzB = (uint32_t)((rowB4 >> 1) & 3);
    uint32_t cB0 = (lane >> 3) & 1;
    uint32_t bRow[2];
    #pragma unroll
    for (int pb = 0; pb < 2; pb++) bRow[pb] = (uint32_t)(rowB4 + pb*16) * 64;

    float acc[4][4][4];
    #pragma unroll
    for (int i = 0; i < 4; i++)
        #pragma unroll
        for (int j = 0; j < 4; j++)
            #pragma unroll
            for (int r = 0; r < 4; r++) acc[i][j][r] = 0.f;

    int nch = Ktot / 32;                // 24*(z+2): even

    // prologue: chunks 0..3 -> stages 0..3
    #pragma unroll
    for (int p = 0; p < 4; p++) {
        uint32_t sb = smem_u + (uint32_t)p * STAGE_B;
        int ko = p * 32;
        cpasync16(sb + offA0, gA + ko); cpasync16(sb + offA1, gA + ko + 8);
        cpasync16(sb + offB,  gB + ko);
        asm volatile("cp.async.commit_group;" ::: "memory");
    }

    #pragma unroll 1
    for (int c = 0; c < nch; c += 2) {
        asm volatile("cp.async.wait_group 2;" ::: "memory");   // chunks c, c+1 landed
        __syncthreads();

        #pragma unroll
        for (int h = 0; h < 2; h++) {
            uint32_t sb = smem_u + (uint32_t)((c + h) & 3) * STAGE_B;
            #pragma unroll
            for (int ks = 0; ks < 2; ks++) {
                uint32_t colA = ((cA0 + 2*ks) ^ swzA) << 4;
                uint32_t colB = ((cB0 + 2*ks) ^ swzB) << 4;
                uint32_t af[4][4], bf[2][4];
                #pragma unroll
                for (int mf = 0; mf < 4; mf++) ldsm4(af[mf], sb + aRow[mf] + colA);
                #pragma unroll
                for (int pb = 0; pb < 2; pb++) ldsm4(bf[pb], sb + 16384 + bRow[pb] + colB);
                #pragma unroll
                for (int mf = 0; mf < 4; mf++) {
                    mma16816(acc[mf][0], af[mf], &bf[0][0]);
                    mma16816(acc[mf][1], af[mf], &bf[0][2]);
                    mma16816(acc[mf][2], af[mf], &bf[1][0]);
                    mma16816(acc[mf][3], af[mf], &bf[1][2]);
                }
            }
        }
        __syncthreads();                                       // reads of c, c+1 done
        #pragma unroll
        for (int h = 0; h < 2; h++) {
            if (c + 4 + h < nch) {
                uint32_t nb = smem_u + (uint32_t)((c + h) & 3) * STAGE_B;
                int ko = (c + 4 + h) * 32;
                cpasync16(nb + offA0, gA + ko); cpasync16(nb + offA1, gA + ko + 8);
                cpasync16(nb + offB,  gB + ko);
            }
            asm volatile("cp.async.commit_group;" ::: "memory");
        }
    }
    asm volatile("cp.async.wait_group 0;" ::: "memory");

    // epilogue: bias + scatter to gathered dst rows
    int r0 = wm*64 + (lane >> 2);
    int cb = n0 + wn*32 + ((lane & 3) << 1);
    const float* bpz = bias.p[z];
    #pragma unroll
    for (int mf = 0; mf < 4; mf++) {
        int row = r0 + mf*16;
        int d0 = s_dst[row], d1 = s_dst[row + 8];
        #pragma unroll
        for (int nf = 0; nf < 4; nf++) {
            float2 bv = *(const float2*)(bpz + cb + nf*8);
            if (d0 >= 0) {
                float2 v; v.x = acc[mf][nf][0] + bv.x; v.y = acc[mf][nf][1] + bv.y;
                *(float2*)(out + (long)d0*Dz + cb + nf*8) = v;
            }
            if (d1 >= 0) {
                float2 v; v.x = acc[mf][nf][2] + bv.x; v.y = acc[mf][nf][3] + bv.y;
                *(float2*)(out + (long)d1*Dz + cb + nf*8) = v;
            }
        }
    }
}

// ---------------- launch ----------------
extern "C" void kernel_launch(void* const* d_in, const int* in_sizes, int n_in,
                              void* d_out, int out_size) {
    const float* feat = (const float*)d_in[0];
    const int*   mask = (const int*)d_in[1];
    // d_in[2] = span_mask (unused; shape only)

    Ptrs7 wp, bp;
    int wi = 0, bi = 0;
    for (int i = 3; i < n_in && i < 17; i++) {
        if (in_sizes[i] == Dz) { if (bi < 7) bp.p[bi++] = (const float*)d_in[i]; }
        else                   { if (wi < 7) wp.p[wi++] = (const float*)d_in[i]; }
    }
    float* out = (float*)d_out;

    prep<<<WBLKS + FBLKS + 1, 256>>>(feat, wp, mask);                  // launch 1

    int tail = (out_size >= Bz*Sz*Dz + Bz*Sz) ? 1 : 0;
    cudaFuncSetAttribute(mma_gemm, cudaFuncAttributeMaxDynamicSharedMemorySize, SMEMREQ);
    mma_gemm<<<dim3(6, 25, 7), 512, SMEMREQ>>>(bp, feat, out, tail);   // launch 2
}